// round 13
// baseline (speedup 1.0000x reference)
#include <cuda_runtime.h>
#include <math.h>

#define TOPK     64
#define TPB      256
#define BPSM     8
#define NBLOCKS  (148 * BPSM)     // 1184 persistent blocks, one wave
#define DDIM     512
#define MAXC_G   8192             // global candidate buffer
#define MAXFILT  512              // filtered candidates (smem)
#define NHBINS   1024
#define SIG_MULT 2.5f

__device__ float        g_alpha[262144];
__device__ float        g_cval[MAXC_G];
__device__ int          g_cidx[MAXC_G];
__device__ int          g_ccount;          // zero-init; reset each run
__device__ unsigned int g_done;            // zero-init; reset each run

// order-preserving float -> uint key
__device__ __forceinline__ unsigned int fkey(float f) {
    unsigned int b = __float_as_uint(f);
    return (b & 0x80000000u) ? ~b : (b | 0x80000000u);
}

__global__ void __launch_bounds__(TPB, BPSM)
fused_kernel(const float* __restrict__ v,
             const float* __restrict__ vs,
             const float* __restrict__ scores,
             float* __restrict__ out, int N) {
    __shared__ float        sv[DDIM];
    __shared__ unsigned int hist[NHBINS];
    __shared__ unsigned int part[TPB];
    __shared__ float        fval[MAXFILT];
    __shared__ int          fidx[MAXFILT];
    __shared__ float        r1[TPB];
    __shared__ float        r2[TPB];
    __shared__ int          ri[TPB];
    __shared__ float        topv[TOPK];
    __shared__ int          topi[TOPK];

    const int tid  = threadIdx.x;
    const int lane = tid & 31;
    const int warp = tid >> 5;

    for (int i = tid; i < DDIM; i += TPB) sv[i] = v[i];
    __syncthreads();

    const float4* vv4 = (const float4*)sv;

    // analytic candidate threshold: alpha ~ N(0, ||v||^2)
    float vn;
    {
        float4 a = vv4[lane], b = vv4[lane + 32], c = vv4[lane + 64], d = vv4[lane + 96];
        vn = a.x*a.x + a.y*a.y + a.z*a.z + a.w*a.w
           + b.x*b.x + b.y*b.y + b.z*b.z + b.w*b.w
           + c.x*c.x + c.y*c.y + c.z*c.z + c.w*c.w
           + d.x*d.x + d.y*d.y + d.z*d.z + d.w*d.w;
#pragma unroll
        for (int o = 16; o; o >>= 1) vn += __shfl_xor_sync(0xffffffffu, vn, o);
    }
    const float thr = SIG_MULT * sqrtf(vn);

    const int gwarp = blockIdx.x * (TPB / 32) + warp;
    const int nw    = NBLOCKS * (TPB / 32);

    // ---------------- phase 1: matvec + threshold append ---------------------
    for (int row = gwarp; row < N; row += nw) {
        const float4* p = (const float4*)(vs + (size_t)row * DDIM);
        float4 x0 = p[lane +  0];
        float4 x1 = p[lane + 32];
        float4 x2 = p[lane + 64];
        float4 x3 = p[lane + 96];
        float4 yy0 = vv4[lane +  0];
        float4 yy1 = vv4[lane + 32];
        float4 yy2 = vv4[lane + 64];
        float4 yy3 = vv4[lane + 96];
        float a0 = x0.x*yy0.x + x0.y*yy0.y + x0.z*yy0.z + x0.w*yy0.w;
        float a1 = x1.x*yy1.x + x1.y*yy1.y + x1.z*yy1.z + x1.w*yy1.w;
        float a2 = x2.x*yy2.x + x2.y*yy2.y + x2.z*yy2.z + x2.w*yy2.w;
        float a3 = x3.x*yy3.x + x3.y*yy3.y + x3.z*yy3.z + x3.w*yy3.w;
        float acc = (a0 + a1) + (a2 + a3);
#pragma unroll
        for (int o = 16; o; o >>= 1) acc += __shfl_xor_sync(0xffffffffu, acc, o);
        if (lane == 0) {
            g_alpha[row] = acc;
            if (acc > thr) {
                int q = atomicAdd(&g_ccount, 1);
                if (q < MAXC_G) { g_cval[q] = acc; g_cidx[q] = row; }
            }
        }
    }

    // ---------------- last-block election ------------------------------------
    __shared__ unsigned int s_isLast;
    __threadfence();
    __syncthreads();
    if (tid == 0)
        s_isLast = (atomicAdd(&g_done, 1u) == NBLOCKS - 1) ? 1u : 0u;
    __syncthreads();
    if (!s_isLast) return;
    __threadfence();

    // ---------------- tail: exact top-K from candidates ----------------------
    int C = g_ccount;
    __shared__ int s_fail;
    if (tid == 0) s_fail = (C < TOPK || C > MAXC_G) ? 1 : 0;
    __syncthreads();

    int F = 0;
    if (!s_fail) {
        // histogram candidate keys (narrow range above thr) into 1024 bins
        for (int i = tid; i < NHBINS; i += TPB) hist[i] = 0u;
        __syncthreads();
        unsigned int base = fkey(thr) >> 16;
        for (int i = tid; i < C; i += TPB) {
            unsigned int b = (fkey(g_cval[i]) >> 16) - base;
            if (b > NHBINS - 1) b = NHBINS - 1;
            atomicAdd(&hist[b], 1u);
        }
        __syncthreads();
        // suffix search for threshold bin
        part[tid] = hist[4*tid] + hist[4*tid+1] + hist[4*tid+2] + hist[4*tid+3];
        __syncthreads();
        __shared__ int s_bstar;
        if (tid == 0) {
            unsigned int cum = 0;
            int g;
            for (g = TPB - 1; g >= 0; g--) {
                if (cum + part[g] >= (unsigned int)TOPK) break;
                cum += part[g];
            }
            if (g < 0) g = 0;
            int b;
            for (b = 4*g + 3; b > 4*g; b--) {
                if (cum + hist[b] >= (unsigned int)TOPK) break;
                cum += hist[b];
            }
            s_bstar = b;
        }
        __syncthreads();
        int bstar = s_bstar;
        // gather candidates with bin >= bstar into smem
        __shared__ int s_nf;
        if (tid == 0) s_nf = 0;
        __syncthreads();
        for (int i = tid; i < C; i += TPB) {
            float val = g_cval[i];
            unsigned int b = (fkey(val) >> 16) - base;
            if (b > NHBINS - 1) b = NHBINS - 1;
            if ((int)b >= bstar) {
                int q = atomicAdd(&s_nf, 1);
                if (q < MAXFILT) { fval[q] = val; fidx[q] = g_cidx[i]; }
            }
        }
        __syncthreads();
        F = s_nf;
        if (tid == 0 && (F > MAXFILT || F < TOPK)) s_fail = 1;
        __syncthreads();
    }

    if (!s_fail) {
        // exact rank-select + softmax + weighted sum over F (~64..200) entries
        float m = -INFINITY;
        for (int i = tid; i < F; i += TPB) m = fmaxf(m, fval[i]);
        r1[tid] = m;
        __syncthreads();
        for (int s = TPB / 2; s; s >>= 1) {
            if (tid < s) r1[tid] = fmaxf(r1[tid], r1[tid + s]);
            __syncthreads();
        }
        m = r1[0];
        __syncthreads();

        float se = 0.f, acc = 0.f;
        for (int i = tid; i < F; i += TPB) {
            float vi = fval[i];
            unsigned int ki = fkey(vi);
            int ii = fidx[i];
            int rank = 0;
            for (int j = 0; j < F; j++) {
                unsigned int kj = fkey(fval[j]);
                rank += (kj > ki) || (kj == ki && fidx[j] < ii);
            }
            if (rank < TOPK) {
                float e = __expf(vi - m);
                se += e;
                acc += e * scores[ii];
            }
        }
        r1[tid] = se;
        r2[tid] = acc;
        __syncthreads();
        for (int s = TPB / 2; s; s >>= 1) {
            if (tid < s) { r1[tid] += r1[tid + s]; r2[tid] += r2[tid + s]; }
            __syncthreads();
        }
        if (tid == 0) out[0] = r2[0] / r1[0];
    } else {
        // robust fallback: 64 exact argmax passes over g_alpha (never on bench data)
        for (int k = 0; k < TOPK; k++) {
            float best = -INFINITY; int bi = 0x7fffffff;
            for (int i = tid; i < N; i += TPB) {
                float a = g_alpha[i];
                if (a > best || (a == best && i < bi)) { best = a; bi = i; }
            }
            r1[tid] = best; ri[tid] = bi;
            __syncthreads();
            for (int s = TPB / 2; s; s >>= 1) {
                if (tid < s) {
                    float ov = r1[tid + s]; int oi = ri[tid + s];
                    if (ov > r1[tid] || (ov == r1[tid] && oi < ri[tid])) {
                        r1[tid] = ov; ri[tid] = oi;
                    }
                }
                __syncthreads();
            }
            if (tid == 0) {
                topv[k] = r1[0]; topi[k] = ri[0];
                g_alpha[ri[0]] = -INFINITY;
            }
            __syncthreads();
        }
        if (tid == 0) {
            float m = topv[0];
            float se = 0.f, acc = 0.f;
            for (int k = 0; k < TOPK; k++) {
                float e = __expf(topv[k] - m);
                se += e;
                acc += e * scores[topi[k]];
            }
            out[0] = acc / se;
        }
    }

    // reset for next graph replay
    if (tid == 0) { g_ccount = 0; g_done = 0u; }
}

// ---------------- launch ------------------------------------------------------
extern "C" void kernel_launch(void* const* d_in, const int* in_sizes, int n_in,
                              void* d_out, int out_size) {
    const float* v      = (const float*)d_in[0];
    const float* vs     = (const float*)d_in[1];
    const float* scores = (const float*)d_in[2];
    float* out = (float*)d_out;
    int N = in_sizes[2];
    (void)n_in; (void)out_size;

    fused_kernel<<<NBLOCKS, TPB>>>(v, vs, scores, out, N);
}